// round 14
// baseline (speedup 1.0000x reference)
#include <cuda_runtime.h>
#include <cuda_bf16.h>
#include <math.h>

// Problem constants (fixed by the reference setup_inputs)
#define BB 1024
#define AA 64
#define DD 1024
#define D4 (DD / 4)          // 256 float4 per row
#define EPS 1e-8f

// Persistent grid: 3 CTAs/SM x 148 SMs, dynamic row fetch.
#define GRID 444

// Pipeline: 2-slot ring of 32 KB stages (8 answers/stage, 8 stages/row),
// continuous across rows (global stage counter keeps mbarrier phases).
#define RING         2
#define ANS_PER_STG  8
#define STAGE_BYTES  (ANS_PER_STG * DD * 4)     // 32768
#define STAGE_F4     (STAGE_BYTES / 16)         // 2048 float4
#define NSTAGES      (AA / ANS_PER_STG)         // 8
#define ROW_BYTES    (AA * DD * 4)              // 262144

#define RING_F4      (RING * STAGE_F4)
#define DSMEM_BYTES  (RING * STAGE_BYTES + DD * 4)   // ring + q = 69632

// Device globals (no allocation allowed). Zero-initialized at module load;
// reset in-kernel so every graph replay starts identically.
__device__ float        g_kl_sum;
__device__ float        g_ndcg_sum;
__device__ unsigned int g_done_count;   // rows finished (epilogues)
__device__ unsigned int g_row;          // dynamic row counter (beyond static GRID)
__device__ unsigned int g_cta_done;     // CTAs exited

__device__ __forceinline__ float warp_sum(float v) {
    #pragma unroll
    for (int o = 16; o > 0; o >>= 1) v += __shfl_xor_sync(0xFFFFFFFFu, v, o);
    return v;
}
__device__ __forceinline__ float warp_max(float v) {
    #pragma unroll
    for (int o = 16; o > 0; o >>= 1) v = fmaxf(v, __shfl_xor_sync(0xFFFFFFFFu, v, o));
    return v;
}

// ---- mbarrier / bulk-async helpers ----
__device__ __forceinline__ unsigned smem_u32(const void* p) {
    return (unsigned)__cvta_generic_to_shared(p);
}
__device__ __forceinline__ void mbar_init(unsigned a, unsigned cnt) {
    asm volatile("mbarrier.init.shared.b64 [%0], %1;" :: "r"(a), "r"(cnt) : "memory");
}
__device__ __forceinline__ void mbar_arrive(unsigned a) {
    asm volatile("mbarrier.arrive.shared.b64 _, [%0];" :: "r"(a) : "memory");
}
__device__ __forceinline__ void mbar_expect_tx(unsigned a, unsigned bytes) {
    asm volatile("mbarrier.arrive.expect_tx.shared.b64 _, [%0], %1;"
                 :: "r"(a), "r"(bytes) : "memory");
}
__device__ __forceinline__ void mbar_wait(unsigned a, unsigned parity) {
    unsigned done;
    asm volatile(
        "{\n\t.reg .pred p;\n\t"
        "mbarrier.try_wait.parity.acquire.cta.shared::cta.b64 p, [%1], %2;\n\t"
        "selp.b32 %0, 1, 0, p;\n\t}"
        : "=r"(done) : "r"(a), "r"(parity) : "memory");
    while (!done) {
        asm volatile(
            "{\n\t.reg .pred p;\n\t"
            "mbarrier.try_wait.parity.acquire.cta.shared::cta.b64 p, [%1], %2, 0x989680;\n\t"
            "selp.b32 %0, 1, 0, p;\n\t}"
            : "=r"(done) : "r"(a), "r"(parity) : "memory");
    }
}
__device__ __forceinline__ void bulk_g2s(unsigned dst, const void* src,
                                         unsigned bytes, unsigned mbar) {
    asm volatile(
        "cp.async.bulk.shared::cta.global.mbarrier::complete_tx::bytes "
        "[%0], [%1], %2, [%3];"
        :: "r"(dst), "l"(src), "r"(bytes), "r"(mbar) : "memory");
}

__global__ __launch_bounds__(512, 3)
void listwise_kernel(const float* __restrict__ q,
                     const float* __restrict__ a_emb,
                     const float* __restrict__ scores,
                     float* __restrict__ out,
                     int out_size) {
    const int tid  = threadIdx.x;
    const int warp = tid >> 5;
    const int lane = tid & 31;

    extern __shared__ __align__(16) float4 dyn[];
    float4* s_buf = dyn;                                    // ring [RING_F4]
    float4* s_q4  = dyn + RING_F4;                          // q row [D4]

    __shared__ float s_part[AA][2];    // per-answer half-dot partials
    __shared__ float s_sim[AA];
    __shared__ float s_sc[AA];
    __shared__ alignas(8) unsigned long long s_full[RING];
    __shared__ alignas(8) unsigned long long s_empty[RING];
    __shared__ int s_b;

    int b = blockIdx.x;                 // static first row per CTA

    if (tid == 0) {
        #pragma unroll
        for (int r = 0; r < RING; r++) {
            mbar_init(smem_u32(&s_full[r]), 1);     // tx-based completion
            mbar_init(smem_u32(&s_empty[r]), 16);   // one arrive per warp
        }
    }
    __syncthreads();

    const char* abase = (const char*)a_emb;

    // Cold prologue for the very first row (fresh barriers — no empty wait).
    if (tid == 0) {
        const char* src = abase + (size_t)b * ROW_BYTES;
        #pragma unroll
        for (int r = 0; r < RING; r++) {
            mbar_expect_tx(smem_u32(&s_full[r]), STAGE_BYTES);
            bulk_g2s(smem_u32(&s_buf[(size_t)r * STAGE_F4]),
                     src + (size_t)r * STAGE_BYTES,
                     STAGE_BYTES, smem_u32(&s_full[r]));
        }
    }

    // Warp w owns (answer w&7, D-half w>>3) within each stage.
    const int a_local = warp & 7;
    const int half    = warp >> 3;
    const int voff    = a_local * 256 + half * 128 + lane;   // float4 idx in stage

    int gs = 0;   // global stage index of current row's first stage

    while (true) {
        // Stage q[b] and scores[b]; overlapped with the in-flight DMA.
        {
            const float4* q4 = reinterpret_cast<const float4*>(q + (size_t)b * DD);
            if (tid < D4) s_q4[tid] = q4[tid];
        }
        if (tid < AA) s_sc[tid] = scores[(size_t)b * AA + tid];
        __syncthreads();

        // Preload this warp's q half-slice (16 regs), reused 8 stages.
        float4 qq[4];
        #pragma unroll
        for (int i = 0; i < 4; i++) qq[i] = s_q4[half * 128 + i * 32 + lane];

        const char* src = abase + (size_t)b * ROW_BYTES;

        for (int j = 0; j < NSTAGES; j++) {
            const int s    = gs + j;
            const int slot = s & 1;
            const int fp   = (s >> 1) & 1;          // full parity for this use

            mbar_wait(smem_u32(&s_full[slot]), fp);

            const float4* vbase = s_buf + (size_t)slot * STAGE_F4 + voff;
            float p = 0.f;
            #pragma unroll
            for (int i = 0; i < 4; i++) {
                float4 v = vbase[i * 32];
                p = fmaf(v.x, qq[i].x, p);
                p = fmaf(v.y, qq[i].y, p);
                p = fmaf(v.z, qq[i].z, p);
                p = fmaf(v.w, qq[i].w, p);
            }
            p = warp_sum(p);
            if (lane == 0) {
                s_part[j * ANS_PER_STG + a_local][half] = p;  // unique writer
                mbar_arrive(smem_u32(&s_empty[slot]));        // stage consumed
            }

            // Producer: refill this slot with stage j+2 of the SAME row.
            // Empty parity for use k+1's fill = k&1 = fp. Row-crossing fills
            // happen below, after the next b is known.
            if (tid == 0 && j < NSTAGES - RING) {
                mbar_wait(smem_u32(&s_empty[slot]), fp);
                mbar_expect_tx(smem_u32(&s_full[slot]), STAGE_BYTES);
                bulk_g2s(smem_u32(&s_buf[(size_t)slot * STAGE_F4]),
                         src + (size_t)(j + RING) * STAGE_BYTES,
                         STAGE_BYTES, smem_u32(&s_full[slot]));
            }
        }
        __syncthreads();   // all s_part written, all drains issued
        gs += NSTAGES;

        // Fetch next row and issue its first 2 fills BEFORE the epilogue, so
        // row-boundary DMA latency hides behind epilogue + next q-load.
        if (tid == 0) {
            int nb = (int)(GRID + atomicAdd(&g_row, 1u));
            s_b = nb;
            if (nb < BB) {
                const char* nsrc = abase + (size_t)nb * ROW_BYTES;
                #pragma unroll
                for (int j2 = 0; j2 < RING; j2++) {
                    const int s2    = gs + j2;
                    const int slot2 = s2 & 1;
                    const int k2    = s2 >> 1;
                    mbar_wait(smem_u32(&s_empty[slot2]), (k2 - 1) & 1);
                    mbar_expect_tx(smem_u32(&s_full[slot2]), STAGE_BYTES);
                    bulk_g2s(smem_u32(&s_buf[(size_t)slot2 * STAGE_F4]),
                             nsrc + (size_t)j2 * STAGE_BYTES,
                             STAGE_BYTES, smem_u32(&s_full[slot2]));
                }
            }
        }

        // ---- Epilogue on warp 0: softmax, KL, NDCG (2 answers/lane) ----
        if (warp == 0) {
            const int a0 = lane;
            const int a1 = lane + 32;
            const float si0 = s_part[a0][0] + s_part[a0][1];
            const float si1 = s_part[a1][0] + s_part[a1][1];
            const float sc0 = s_sc[a0],  sc1 = s_sc[a1];
            s_sim[a0] = si0;
            s_sim[a1] = si1;
            __syncwarp();

            float m  = warp_max(fmaxf(si0, si1));
            float e0 = expf(si0 - m), e1 = expf(si1 - m);
            float Z  = warp_sum(e0 + e1);
            float p0 = e0 / Z, p1 = e1 / Z;

            float ms = warp_max(fmaxf(sc0, sc1));
            float t0 = expf(sc0 - ms), t1 = expf(sc1 - ms);
            float Zt = warp_sum(t0 + t1);
            float logZt = logf(Zt);

            float lt0 = (sc0 - ms) - logZt;
            float lt1 = (sc1 - ms) - logZt;
            float kl  = (t0 / Zt) * (lt0 - logf(p0 + EPS))
                      + (t1 / Zt) * (lt1 - logf(p1 + EPS));
            kl = warp_sum(kl);

            // ranks, stable tie-break by index == jax stable argsort(-x)
            int r0 = 0, r1 = 0, i0 = 0, i1 = 0;
            #pragma unroll
            for (int j = 0; j < AA; j++) {
                float sj = s_sim[j];
                float cj = s_sc[j];
                r0 += (sj > si0) || (sj == si0 && j < a0);
                r1 += (sj > si1) || (sj == si1 && j < a1);
                i0 += (cj > sc0) || (cj == sc0 && j < a0);
                i1 += (cj > sc1) || (cj == sc1 && j < a1);
            }
            float pred_dcg  = sc0 / log2f((float)(r0 + 2)) + sc1 / log2f((float)(r1 + 2));
            float ideal_dcg = sc0 / log2f((float)(i0 + 2)) + sc1 / log2f((float)(i1 + 2));
            pred_dcg  = warp_sum(pred_dcg);
            ideal_dcg = warp_sum(ideal_dcg);

            if (lane == 0) {
                atomicAdd(&g_kl_sum, kl);
                atomicAdd(&g_ndcg_sum, pred_dcg / (ideal_dcg + EPS));
                __threadfence();
                unsigned int old = atomicAdd(&g_done_count, 1u);
                if (old == BB - 1) {
                    // All BB rows' adds are ordered before their bumps.
                    float klsum = atomicAdd(&g_kl_sum, 0.0f);
                    float ndsum = atomicAdd(&g_ndcg_sum, 0.0f);
                    out[0] = klsum / (float)BB;
                    if (out_size > 1) out[1] = ndsum / (float)BB;
                    g_kl_sum     = 0.0f;
                    g_ndcg_sum   = 0.0f;
                    g_done_count = 0u;
                }
            }
        }
        __syncthreads();   // s_b visible; epilogue done before smem reuse
        b = s_b;
        if (b >= BB) break;
    }

    // CTA-level cleanup: only after ALL CTAs have exited their fetch loop can
    // g_row be reset (a straggler's terminating atomicAdd must land first).
    if (tid == 0) {
        __threadfence();
        unsigned int old = atomicAdd(&g_cta_done, 1u);
        if (old == GRID - 1) {
            g_row      = 0u;
            g_cta_done = 0u;
        }
    }
}

extern "C" void kernel_launch(void* const* d_in, const int* in_sizes, int n_in,
                              void* d_out, int out_size) {
    const float* q      = (const float*)d_in[0];   // [B, D]
    const float* a_emb  = (const float*)d_in[1];   // [B, A, D]
    const float* scores = (const float*)d_in[2];   // [B, A]
    (void)in_sizes; (void)n_in;
    float* out = (float*)d_out;

    // Dynamic smem > 48 KB static limit; host attribute call, graph-capture
    // safe (not a stream op), idempotent every launch.
    cudaFuncSetAttribute(listwise_kernel,
                         cudaFuncAttributeMaxDynamicSharedMemorySize,
                         DSMEM_BYTES);

    listwise_kernel<<<GRID, 512, DSMEM_BYTES>>>(q, a_emb, scores, out, out_size);
}